// round 5
// baseline (speedup 1.0000x reference)
#include <cuda_runtime.h>
#include <cuda_bf16.h>
#include <cstdint>

// Problem constants
#define BATCH 4096
#define DIM   768
#define FEAT  16384
#define TOPK  64

// GEMM tile config: CTA 256x128, 8 warps (4x2), warp tile 64x64
#define BM 256
#define BN 128
#define BK 16
#define NSTAGE 4
#define GTHREADS 256
#define NCHUNK (DIM / BK)          // 48
// stage layout (uint32 offsets), rows of 16 floats, no padding
#define OFF_AH 0
#define OFF_AL (BM * BK)                  // 4096
#define OFF_BH (2 * BM * BK)              // 8192
#define OFF_BL (2 * BM * BK + BN * BK)    // 10240
#define STAGE_U32 (2 * BM * BK + 2 * BN * BK)   // 12288
#define STAGE_BYTES (STAGE_U32 * 4)             // 49152
#define SMEM_BYTES (NSTAGE * STAGE_BYTES)       // 196608

// topk smem: keys[FEAT] + hist[2048]
#define TK_SMEM_BYTES ((FEAT + 2048) * 4)       // 73728

// ---------------- scratch (device globals; no allocation allowed) ----------
__device__ float g_pre[(size_t)BATCH * FEAT];             // pre-activations (256 MB)
__device__ float g_WdT[(size_t)FEAT * DIM];               // W_dec transposed (50 MB)
__device__ int   g_tidx[BATCH * TOPK];
__device__ float g_tval[BATCH * TOPK];
// tf32 hi/lo splits (bit patterns), k-PERMUTED within each 16-k group:
// stored index within group = (k%4)*4 + k/4
__device__ uint32_t g_xh[BATCH * DIM];
__device__ uint32_t g_xl[BATCH * DIM];
__device__ uint32_t g_wh[(size_t)FEAT * DIM];
__device__ uint32_t g_wl[(size_t)FEAT * DIM];

// ---------------- helpers ---------------------------------------------------
__device__ __forceinline__ uint32_t smem_u32(const void* p) {
    uint32_t a;
    asm("{ .reg .u64 t; cvta.to.shared.u64 t, %1; cvt.u32.u64 %0, t; }" : "=r"(a) : "l"(p));
    return a;
}
__device__ __forceinline__ void split_tf32(float v, uint32_t& hi, uint32_t& lo) {
    uint32_t h;
    asm("cvt.rna.tf32.f32 %0, %1;" : "=r"(h) : "f"(v));
    float r = v - __uint_as_float(h);
    uint32_t l;
    asm("cvt.rna.tf32.f32 %0, %1;" : "=r"(l) : "f"(r));
    hi = h; lo = l;
}
__device__ __forceinline__ void mma_tf32_4(float* c, uint32_t a0, uint32_t a1,
                                           uint32_t a2, uint32_t a3,
                                           uint32_t b0, uint32_t b1) {
    asm volatile(
        "mma.sync.aligned.m16n8k8.row.col.f32.tf32.tf32.f32 "
        "{%0,%1,%2,%3}, {%4,%5,%6,%7}, {%8,%9}, {%0,%1,%2,%3};\n"
        : "+f"(c[0]), "+f"(c[1]), "+f"(c[2]), "+f"(c[3])
        : "r"(a0), "r"(a1), "r"(a2), "r"(a3), "r"(b0), "r"(b1));
}
#define CP_ASYNC16(dst, src) \
    asm volatile("cp.async.cg.shared.global [%0], [%1], 16;" :: "r"(dst), "l"(src))
#define CP_COMMIT() asm volatile("cp.async.commit_group;" ::: "memory")
#define CP_WAIT(n)  asm volatile("cp.async.wait_group %0;" :: "n"(n) : "memory")

// permuted target offset within a row: group base + (k%4)*4 + k/4
__device__ __forceinline__ int kperm(int k) {
    return (k & ~15) + ((k & 3) << 2) + ((k >> 2) & 3);
}

// ---------------- kernel: tf32 split of (x - b_dec), permuted ----------------
__global__ void __launch_bounds__(256) split_x_kernel(const float* __restrict__ x,
                                                      const float* __restrict__ b_dec) {
    int i = blockIdx.x * 256 + threadIdx.x;
    if (i >= BATCH * DIM) return;
    int k = i % DIM;
    float a = x[i] - b_dec[k];
    uint32_t h, l;
    split_tf32(a, h, l);
    int dst = (i - k) + kperm(k);
    g_xh[dst] = h; g_xl[dst] = l;
}

// ---------------- kernel: tf32 split of W_enc, permuted ----------------------
__global__ void __launch_bounds__(256) split_w_kernel(const float* __restrict__ W) {
    size_t i = (size_t)blockIdx.x * 256 + threadIdx.x;
    if (i >= (size_t)FEAT * DIM) return;
    int k = (int)(i % DIM);
    uint32_t h, l;
    split_tf32(W[i], h, l);
    size_t dst = (i - k) + kperm(k);
    g_wh[dst] = h; g_wl[dst] = l;
}

// ---------------- kernel: transpose W_dec [D,F] -> [F,D] ---------------------
__global__ void transpose_wdec_kernel(const float* __restrict__ Wd) {
    __shared__ float tile[32][33];
    int f0 = blockIdx.x * 32;
    int d0 = blockIdx.y * 32;
    int tx = threadIdx.x, ty = threadIdx.y;   // block (32, 8)
    #pragma unroll
    for (int i = 0; i < 32; i += 8)
        tile[ty + i][tx] = Wd[(size_t)(d0 + ty + i) * FEAT + f0 + tx];
    __syncthreads();
    #pragma unroll
    for (int i = 0; i < 32; i += 8)
        g_WdT[(size_t)(f0 + ty + i) * DIM + d0 + tx] = tile[tx][ty + i];
}

// ---------------- kernel: encode GEMM, 3xTF32 mma.sync -----------------------
// g_pre[m,n] = sum_k xc[m,k] * W_enc[n,k] + b_enc[n]
__device__ __forceinline__ void load_stage(uint32_t sbase, int chunk, int m0, int n0, int tid) {
    const int k0 = chunk * BK;
    #pragma unroll
    for (int p = 0; p < 12; p++) {
        int s = tid + p * GTHREADS;          // 0..3071
        if (s < 1024) {                      // A_hi: 256 rows x 4 segs
            int r = s >> 2, q = s & 3;
            CP_ASYNC16(sbase + (OFF_AH + r * BK + q * 4) * 4,
                       g_xh + (size_t)(m0 + r) * DIM + k0 + q * 4);
        } else if (s < 2048) {               // A_lo
            int s2 = s - 1024;
            int r = s2 >> 2, q = s2 & 3;
            CP_ASYNC16(sbase + (OFF_AL + r * BK + q * 4) * 4,
                       g_xl + (size_t)(m0 + r) * DIM + k0 + q * 4);
        } else if (s < 2560) {               // B_hi: 128 rows x 4 segs
            int s2 = s - 2048;
            int r = s2 >> 2, q = s2 & 3;
            CP_ASYNC16(sbase + (OFF_BH + r * BK + q * 4) * 4,
                       g_wh + (size_t)(n0 + r) * DIM + k0 + q * 4);
        } else {                             // B_lo
            int s2 = s - 2560;
            int r = s2 >> 2, q = s2 & 3;
            CP_ASYNC16(sbase + (OFF_BL + r * BK + q * 4) * 4,
                       g_wl + (size_t)(n0 + r) * DIM + k0 + q * 4);
        }
    }
}

__global__ void __launch_bounds__(GTHREADS, 1) encode_gemm_kernel(
    const float* __restrict__ bias) {
    extern __shared__ __align__(16) char smem[];
    const int tid = threadIdx.x;
    const int lane = tid & 31;
    const int wid = tid >> 5;
    const int warp_m = wid >> 1;     // 0..3 -> 64-row slab
    const int warp_n = wid & 1;      // 0..1 -> 64-col slab
    const int m0 = blockIdx.y * BM;
    const int n0 = blockIdx.x * BN;
    const uint32_t smem_base = smem_u32(smem);

    float acc[4][8][4];
    #pragma unroll
    for (int i = 0; i < 4; i++)
        #pragma unroll
        for (int j = 0; j < 8; j++)
            #pragma unroll
            for (int r = 0; r < 4; r++) acc[i][j][r] = 0.f;

    #pragma unroll
    for (int c = 0; c < NSTAGE - 1; c++) {
        load_stage(smem_base + c * STAGE_BYTES, c, m0, n0, tid);
        CP_COMMIT();
    }

    const int lr = lane >> 2;     // 0..7
    const int lc = lane & 3;      // 0..3

    for (int chunk = 0; chunk < NCHUNK; chunk++) {
        CP_WAIT(NSTAGE - 2);
        __syncthreads();

        // issue next stage immediately (overlaps with compute below)
        int next = chunk + NSTAGE - 1;
        if (next < NCHUNK)
            load_stage(smem_base + (next & (NSTAGE - 1)) * STAGE_BYTES, next, m0, n0, tid);
        CP_COMMIT();   // unconditional: keeps group-count semantics at the tail

        const int st = chunk & (NSTAGE - 1);
        const uint4* s4 = (const uint4*)(smem + st * STAGE_BYTES);
        const uint4* sAh = s4 + OFF_AH / 4;
        const uint4* sAl = s4 + OFF_AL / 4;
        const uint4* sBh = s4 + OFF_BH / 4;
        const uint4* sBl = s4 + OFF_BL / 4;

        // B fragments: one LDS.128 per (nt, hi/lo) covers both k8 halves
        uint4 Bh[8], Bl[8];
        #pragma unroll
        for (int nt = 0; nt < 8; nt++) {
            int n = warp_n * 64 + nt * 8 + lr;
            Bh[nt] = sBh[n * 4 + lc];
            Bl[nt] = sBl[n * 4 + lc];
        }

        #pragma unroll
        for (int mt = 0; mt < 4; mt++) {
            int m = warp_m * 64 + mt * 16 + lr;
            uint4 Ah0 = sAh[m * 4 + lc];
            uint4 Ah1 = sAh[(m + 8) * 4 + lc];
            uint4 Al0 = sAl[m * 4 + lc];
            uint4 Al1 = sAl[(m + 8) * 4 + lc];
            // k8 = 0: a = {v.x(row), v.x(row+8), v.y(row), v.y(row+8)}
            #pragma unroll
            for (int nt = 0; nt < 8; nt++)
                mma_tf32_4(acc[mt][nt], Ah0.x, Ah1.x, Ah0.y, Ah1.y, Bh[nt].x, Bh[nt].y);
            #pragma unroll
            for (int nt = 0; nt < 8; nt++)
                mma_tf32_4(acc[mt][nt], Ah0.x, Ah1.x, Ah0.y, Ah1.y, Bl[nt].x, Bl[nt].y);
            #pragma unroll
            for (int nt = 0; nt < 8; nt++)
                mma_tf32_4(acc[mt][nt], Al0.x, Al1.x, Al0.y, Al1.y, Bh[nt].x, Bh[nt].y);
            // k8 = 1: a = {v.z, v.z(+8), v.w, v.w(+8)}, b = {.z, .w}
            #pragma unroll
            for (int nt = 0; nt < 8; nt++)
                mma_tf32_4(acc[mt][nt], Ah0.z, Ah1.z, Ah0.w, Ah1.w, Bh[nt].z, Bh[nt].w);
            #pragma unroll
            for (int nt = 0; nt < 8; nt++)
                mma_tf32_4(acc[mt][nt], Ah0.z, Ah1.z, Ah0.w, Ah1.w, Bl[nt].z, Bl[nt].w);
            #pragma unroll
            for (int nt = 0; nt < 8; nt++)
                mma_tf32_4(acc[mt][nt], Al0.z, Al1.z, Al0.w, Al1.w, Bh[nt].z, Bh[nt].w);
        }
        __syncthreads();
    }

    // epilogue: acc + bias -> g_pre
    #pragma unroll
    for (int mt = 0; mt < 4; mt++) {
        #pragma unroll
        for (int nt = 0; nt < 8; nt++) {
            int row = m0 + warp_m * 64 + mt * 16 + lr;
            int col = n0 + warp_n * 64 + nt * 8 + 2 * lc;
            float2 bv = *(const float2*)&bias[col];
            float2 o0 = make_float2(acc[mt][nt][0] + bv.x, acc[mt][nt][1] + bv.y);
            float2 o1 = make_float2(acc[mt][nt][2] + bv.x, acc[mt][nt][3] + bv.y);
            *(float2*)&g_pre[(size_t)row * FEAT + col] = o0;
            *(float2*)&g_pre[(size_t)(row + 8) * FEAT + col] = o1;
        }
    }
}

// ---------------- helpers for topk ------------------------------------------
__device__ __forceinline__ unsigned fkey(float v) {
    unsigned u = __float_as_uint(v);
    return (u & 0x80000000u) ? ~u : (u | 0x80000000u);
}
__device__ __forceinline__ float key_to_float(unsigned k) {
    unsigned u = (k & 0x80000000u) ? (k & 0x7fffffffu) : ~k;
    return __uint_as_float(u);
}

// ---------------- kernel: exact top-64 per row (radix select, smem-cached) ---
__global__ void __launch_bounds__(256) topk_kernel() {
    extern __shared__ uint32_t tk[];        // keys[FEAT] then hist[2048]
    uint32_t* keys = tk;
    uint32_t* hist = tk + FEAT;

    const int row = blockIdx.x;
    const int tid = threadIdx.x;

    __shared__ unsigned tsum[256];
    __shared__ unsigned sh_digit, sh_need;
    __shared__ int cnt, eqn;
    __shared__ int eqbuf[256];

    for (int i = tid; i < 2048; i += 256) hist[i] = 0;
    __syncthreads();

    // single global read: build keys + level-0 histogram (bits 31..21)
    const float4* p4 = (const float4*)(g_pre + (size_t)row * FEAT);
    #pragma unroll
    for (int it = 0; it < 16; it++) {
        int i = tid + it * 256;             // float4 index (4096 total)
        float4 v = p4[i];
        unsigned k0 = fkey(v.x), k1 = fkey(v.y), k2 = fkey(v.z), k3 = fkey(v.w);
        keys[i * 4 + 0] = k0; keys[i * 4 + 1] = k1;
        keys[i * 4 + 2] = k2; keys[i * 4 + 3] = k3;
        atomicAdd(&hist[k0 >> 21], 1u);
        atomicAdd(&hist[k1 >> 21], 1u);
        atomicAdd(&hist[k2 >> 21], 1u);
        atomicAdd(&hist[k3 >> 21], 1u);
    }
    __syncthreads();

    unsigned prefix = 0;
    unsigned need = TOPK;
    const int shifts[3]  = {21, 10, 0};
    const int bitsArr[3] = {11, 11, 10};

    for (int lvl = 0; lvl < 3; lvl++) {
        const int shift = shifts[lvl];
        const int bits = bitsArr[lvl];
        const int nb = 1 << bits;

        if (lvl > 0) {
            for (int i = tid; i < nb; i += 256) hist[i] = 0;
            __syncthreads();
            for (int it = 0; it < FEAT / 256; it++) {
                unsigned key = keys[tid + it * 256];
                if ((key >> (shift + bits)) == prefix)
                    atomicAdd(&hist[(key >> shift) & (nb - 1)], 1u);
            }
            __syncthreads();
        }

        // parallel digit selection (descending)
        const int stride = nb / 256;
        unsigned s = 0;
        #pragma unroll 4
        for (int j = 0; j < stride; j++) s += hist[tid * stride + j];
        tsum[tid] = s;
        __syncthreads();
        if (tid == 0) {
            unsigned cum = 0;
            int t = 255;
            for (; t >= 0; t--) {
                if (cum + tsum[t] >= need) break;
                cum += tsum[t];
            }
            unsigned dig = 0;
            for (int b = (t + 1) * stride - 1; b >= t * stride; b--) {
                unsigned h = hist[b];
                if (cum + h >= need) { dig = (unsigned)b; break; }
                cum += h;
            }
            sh_digit = dig;
            sh_need = need - cum;
        }
        __syncthreads();
        prefix = (prefix << bits) | sh_digit;
        need = sh_need;
        __syncthreads();
    }

    const unsigned T = prefix;              // exact key of K-th largest
    if (tid == 0) { cnt = 0; eqn = 0; }
    __syncthreads();

    for (int it = 0; it < FEAT / 256; it++) {
        int i = tid + it * 256;
        unsigned key = keys[i];
        if (key > T) {
            int s2 = atomicAdd(&cnt, 1);
            g_tidx[row * TOPK + s2] = i;
            g_tval[row * TOPK + s2] = key_to_float(key);
        } else if (key == T) {
            int e = atomicAdd(&eqn, 1);
            if (e < 256) eqbuf[e] = i;
        }
    }
    __syncthreads();

    if (tid == 0) {
        int ne = eqn; if (ne > 256) ne = 256;
        for (int a = 1; a < ne; a++) {
            int v = eqbuf[a]; int b = a - 1;
            while (b >= 0 && eqbuf[b] > v) { eqbuf[b + 1] = eqbuf[b]; b--; }
            eqbuf[b + 1] = v;
        }
        float tv = key_to_float(T);
        int base = cnt;
        for (int j = 0; j < (int)need; j++) {
            g_tidx[row * TOPK + base + j] = eqbuf[j];
            g_tval[row * TOPK + base + j] = tv;
        }
    }
}

// ---------------- kernel: sparse decode ---------------------------------------
__global__ void __launch_bounds__(256) decode_kernel(const float* __restrict__ b_dec,
                                                     float* __restrict__ out) {
    const int row = blockIdx.x;
    const int t = threadIdx.x;
    __shared__ int   sidx[TOPK];
    __shared__ float sval[TOPK];
    if (t < TOPK) {
        sidx[t] = g_tidx[row * TOPK + t];
        sval[t] = g_tval[row * TOPK + t];
    }
    __syncthreads();

    float a0 = b_dec[t];
    float a1 = b_dec[t + 256];
    float a2 = b_dec[t + 512];
    #pragma unroll 4
    for (int k = 0; k < TOPK; k++) {
        const float* w = g_WdT + (size_t)sidx[k] * DIM;
        float v = sval[k];
        a0 += v * w[t];
        a1 += v * w[t + 256];
        a2 += v * w[t + 512];
    }
    float* o = out + (size_t)row * DIM;
    o[t] = a0;
    o[t + 256] = a1;
    o[t + 512] = a2;
}

// ---------------- launcher -----------------------------------------------------
extern "C" void kernel_launch(void* const* d_in, const int* in_sizes, int n_in,
                              void* d_out, int out_size) {
    const float* x     = (const float*)d_in[0];
    const float* W_enc = (const float*)d_in[1];
    const float* b_enc = (const float*)d_in[2];
    const float* W_dec = (const float*)d_in[3];
    const float* b_dec = (const float*)d_in[4];
    float* out = (float*)d_out;

    cudaFuncSetAttribute(encode_gemm_kernel,
                         cudaFuncAttributeMaxDynamicSharedMemorySize, SMEM_BYTES);
    cudaFuncSetAttribute(topk_kernel,
                         cudaFuncAttributeMaxDynamicSharedMemorySize, TK_SMEM_BYTES);

    split_x_kernel<<<(BATCH * DIM + 255) / 256, 256>>>(x, b_dec);
    split_w_kernel<<<(int)(((size_t)FEAT * DIM + 255) / 256), 256>>>(W_enc);

    dim3 tgrid(FEAT / 32, DIM / 32);
    dim3 tblk(32, 8);
    transpose_wdec_kernel<<<tgrid, tblk>>>(W_dec);

    dim3 ggrid(FEAT / BN, BATCH / BM);
    encode_gemm_kernel<<<ggrid, GTHREADS, SMEM_BYTES>>>(b_enc);

    topk_kernel<<<BATCH, 256, TK_SMEM_BYTES>>>();

    decode_kernel<<<BATCH, 256>>>(b_dec, out);
}